// round 6
// baseline (speedup 1.0000x reference)
#include <cuda_runtime.h>

// DiffJPEG forward: out = jpeg_compress(clip(x,0,1), quality=75)
// x, out: (16, 3, 512, 512) float32
//
// One CTA per 32x16 pixel region: 8 Y blocks + 2 Cb + 2 Cr (12 blocks of 8x8).
// 96 threads, one thread per block-row. Butterfly DCT/IDCT in registers;
// SMEM only for the two 8x8 transposes, quant tables, and chroma handoff.

#define IMG_H 512
#define IMG_W 512
#define BATCH 16

#define A1 0.4903926402016152f
#define A2 0.4619397662556434f
#define A3 0.4157348061512726f
#define A4 0.3535533905932738f
#define A5 0.2777851165098011f
#define A6 0.1913417161825449f
#define A7 0.0975451610080642f

__constant__ float c_QY[8][8] = {
    {16, 11, 10, 16, 24, 40, 51, 61},
    {12, 12, 14, 19, 26, 58, 60, 55},
    {14, 13, 16, 24, 40, 57, 69, 56},
    {14, 17, 22, 29, 51, 87, 80, 62},
    {18, 22, 37, 56, 68, 109, 103, 77},
    {24, 35, 55, 64, 81, 104, 113, 92},
    {49, 64, 78, 87, 103, 121, 120, 101},
    {72, 92, 95, 98, 112, 100, 103, 99},
};
__constant__ float c_QC[8][8] = {
    {17, 18, 24, 47, 99, 99, 99, 99},
    {18, 21, 26, 66, 99, 99, 99, 99},
    {24, 26, 56, 99, 99, 99, 99, 99},
    {47, 66, 99, 99, 99, 99, 99, 99},
    {99, 99, 99, 99, 99, 99, 99, 99},
    {99, 99, 99, 99, 99, 99, 99, 99},
    {99, 99, 99, 99, 99, 99, 99, 99},
    {99, 99, 99, 99, 99, 99, 99, 99},
};

// forward 8-point DCT-II: out[u] = sum_x D[u][x] in[x], in place
__device__ __forceinline__ void fwd1d(float d[8])
{
    float s0 = d[0] + d[7], s1 = d[1] + d[6], s2 = d[2] + d[5], s3 = d[3] + d[4];
    float t0 = d[0] - d[7], t1 = d[1] - d[6], t2 = d[2] - d[5], t3 = d[3] - d[4];
    d[0] = A4 * (s0 + s1 + s2 + s3);
    d[2] = A2 * s0 + A6 * s1 - A6 * s2 - A2 * s3;
    d[4] = A4 * (s0 - s1 - s2 + s3);
    d[6] = A6 * s0 - A2 * s1 + A2 * s2 - A6 * s3;
    d[1] = A1 * t0 + A3 * t1 + A5 * t2 + A7 * t3;
    d[3] = A3 * t0 - A7 * t1 - A1 * t2 - A5 * t3;
    d[5] = A5 * t0 - A1 * t1 + A7 * t2 + A3 * t3;
    d[7] = A7 * t0 - A5 * t1 + A3 * t2 - A1 * t3;
}

// inverse: out[x] = sum_u D[u][x] in[u], in place
__device__ __forceinline__ void inv1d(float d[8])
{
    float e0 = A4 * d[0] + A2 * d[2] + A4 * d[4] + A6 * d[6];
    float e1 = A4 * d[0] + A6 * d[2] - A4 * d[4] - A2 * d[6];
    float e2 = A4 * d[0] - A6 * d[2] - A4 * d[4] + A2 * d[6];
    float e3 = A4 * d[0] - A2 * d[2] + A4 * d[4] - A6 * d[6];
    float o0 = A1 * d[1] + A3 * d[3] + A5 * d[5] + A7 * d[7];
    float o1 = A3 * d[1] - A7 * d[3] - A1 * d[5] - A5 * d[7];
    float o2 = A5 * d[1] - A1 * d[3] + A7 * d[5] + A3 * d[7];
    float o3 = A7 * d[1] - A5 * d[3] + A3 * d[5] - A1 * d[7];
    d[0] = e0 + o0; d[7] = e0 - o0;
    d[1] = e1 + o1; d[6] = e1 - o1;
    d[2] = e2 + o2; d[5] = e2 - o2;
    d[3] = e3 + o3; d[4] = e3 - o3;
}

// Full fwd-DCT -> quantize -> inv-DCT; thread holds row r of the block.
// S: per-block 8x9 transpose scratch; Q/Qi: quant table and reciprocal.
__device__ __forceinline__ void transform8(float v[8], float (*S)[9],
                                           const float (*Q)[9],
                                           const float (*Qi)[9], int r)
{
    fwd1d(v);                                   // row DCT
#pragma unroll
    for (int j = 0; j < 8; j++) S[j][r] = v[j]; // transpose 1
    __syncwarp();
#pragma unroll
    for (int j = 0; j < 8; j++) v[j] = S[r][j];
    __syncwarp();
    fwd1d(v);                                   // column DCT -> coef^T row r
#pragma unroll
    for (int j = 0; j < 8; j++)                 // quantize: coef[j][r]
        v[j] = rintf(v[j] * Qi[j][r]) * Q[j][r];
    inv1d(v);                                   // column IDCT
#pragma unroll
    for (int j = 0; j < 8; j++) S[j][r] = v[j]; // transpose 2
    __syncwarp();
#pragma unroll
    for (int j = 0; j < 8; j++) v[j] = S[r][j];
    __syncwarp();
    inv1d(v);                                   // row IDCT -> rec row r
}

__global__ __launch_bounds__(96)
void diffjpeg_kernel(const float* __restrict__ x, float* __restrict__ out)
{
    __shared__ float sP[2][16][20];     // horizontally-averaged chroma partials
    __shared__ float sS[12][8][9];      // per-block transpose scratch
    __shared__ float sQ[2][8][9];       // quant tables * factor
    __shared__ float sQi[2][8][9];      // reciprocals
    __shared__ __align__(16) float sCrec[2][8][20];   // reconstructed chroma (centered)

    const int tid = threadIdx.x;
    const int bx0 = blockIdx.x * 32;
    const int by0 = blockIdx.y * 16;
    const size_t plane  = (size_t)IMG_H * IMG_W;
    const size_t ibase  = (size_t)blockIdx.z * 3 * plane;

    if (tid < 64) {
        int u = tid >> 3, vv = tid & 7;
        float qy = c_QY[u][vv] * 0.5f;   // quality 75 -> factor 0.5
        float qc = c_QC[u][vv] * 0.5f;
        sQ[0][u][vv]  = qy;
        sQ[1][u][vv]  = qc;
        sQi[0][u][vv] = 1.0f / qy;
        sQi[1][u][vv] = 1.0f / qc;
    }

    // luma geometry
    const int blk  = tid >> 3, r = tid & 7;
    const int bcol = blk & 3,  brow = blk >> 2;
    const int lrow = brow * 8 + r;

    float v[8];

    if (tid < 64) {
        // ---- luma: load row, color convert, emit chroma partials ----
        const int grow = by0 + lrow;
        const int gcol = bx0 + bcol * 8;
        const float* pr = x + ibase + (size_t)grow * IMG_W + gcol;

        float4 r0 = *(const float4*)pr,               r1 = *(const float4*)(pr + 4);
        float4 g0 = *(const float4*)(pr + plane),     g1 = *(const float4*)(pr + plane + 4);
        float4 b0 = *(const float4*)(pr + 2 * plane), b1 = *(const float4*)(pr + 2 * plane + 4);

        float R[8] = {r0.x, r0.y, r0.z, r0.w, r1.x, r1.y, r1.z, r1.w};
        float G[8] = {g0.x, g0.y, g0.z, g0.w, g1.x, g1.y, g1.z, g1.w};
        float B[8] = {b0.x, b0.y, b0.z, b0.w, b1.x, b1.y, b1.z, b1.w};

        float cb[8], cr[8];
#pragma unroll
        for (int i = 0; i < 8; i++) {
            float rr = fminf(fmaxf(R[i], 0.f), 1.f) * 255.f;
            float gg = fminf(fmaxf(G[i], 0.f), 1.f) * 255.f;
            float bb = fminf(fmaxf(B[i], 0.f), 1.f) * 255.f;
            v[i]  =  0.299f    * rr + 0.587f    * gg + 0.114f    * bb - 128.f;
            cb[i] = -0.168736f * rr - 0.331264f * gg + 0.5f      * bb + 128.f;
            cr[i] =  0.5f      * rr - 0.418688f * gg - 0.081312f * bb + 128.f;
        }
        *(float4*)&sP[0][lrow][bcol * 4] =
            make_float4(0.5f * (cb[0] + cb[1]), 0.5f * (cb[2] + cb[3]),
                        0.5f * (cb[4] + cb[5]), 0.5f * (cb[6] + cb[7]));
        *(float4*)&sP[1][lrow][bcol * 4] =
            make_float4(0.5f * (cr[0] + cr[1]), 0.5f * (cr[2] + cr[3]),
                        0.5f * (cr[4] + cr[5]), 0.5f * (cr[6] + cr[7]));
    }
    __syncthreads();

    if (tid < 64) {
        transform8(v, sS[blk], sQ[0], sQi[0], r);
    } else {
        // ---- chroma: finish 2x2 downsample, transform, publish ----
        const int t  = tid - 64;
        const int ch = t >> 4;
        const int s2 = t & 15;
        const int bc = s2 >> 3, cr_ = s2 & 7;

        float4 a0 = *(const float4*)&sP[ch][2 * cr_][bc * 8];
        float4 a1 = *(const float4*)&sP[ch][2 * cr_][bc * 8 + 4];
        float4 b0 = *(const float4*)&sP[ch][2 * cr_ + 1][bc * 8];
        float4 b1 = *(const float4*)&sP[ch][2 * cr_ + 1][bc * 8 + 4];

        v[0] = 0.5f * (a0.x + b0.x) - 128.f;
        v[1] = 0.5f * (a0.y + b0.y) - 128.f;
        v[2] = 0.5f * (a0.z + b0.z) - 128.f;
        v[3] = 0.5f * (a0.w + b0.w) - 128.f;
        v[4] = 0.5f * (a1.x + b1.x) - 128.f;
        v[5] = 0.5f * (a1.y + b1.y) - 128.f;
        v[6] = 0.5f * (a1.z + b1.z) - 128.f;
        v[7] = 0.5f * (a1.w + b1.w) - 128.f;

        transform8(v, sS[8 + ch * 2 + bc], sQ[1], sQi[1], cr_);

        *(float4*)&sCrec[ch][cr_][bc * 8]     = make_float4(v[0], v[1], v[2], v[3]);
        *(float4*)&sCrec[ch][cr_][bc * 8 + 4] = make_float4(v[4], v[5], v[6], v[7]);
    }
    __syncthreads();

    // ---- output: luma thread writes its own rec row directly ----
    if (tid < 64) {
        const int crow = lrow >> 1;
        float4 cb4 = *(const float4*)&sCrec[0][crow][bcol * 4];
        float4 cr4 = *(const float4*)&sCrec[1][crow][bcol * 4];
        float cbm[8] = {cb4.x, cb4.x, cb4.y, cb4.y, cb4.z, cb4.z, cb4.w, cb4.w};
        float crm[8] = {cr4.x, cr4.x, cr4.y, cr4.y, cr4.z, cr4.z, cr4.w, cr4.w};

        float Rr[8], Gg[8], Bb[8];
#pragma unroll
        for (int k = 0; k < 8; k++) {
            float yv = v[k] + 128.f;
            float r2 = yv + 1.402f * crm[k];
            float g2 = yv - 0.344136f * cbm[k] - 0.714136f * crm[k];
            float b2 = yv + 1.772f * cbm[k];
            Rr[k] = fminf(fmaxf(r2, 0.f), 255.f) * (1.f / 255.f);
            Gg[k] = fminf(fmaxf(g2, 0.f), 255.f) * (1.f / 255.f);
            Bb[k] = fminf(fmaxf(b2, 0.f), 255.f) * (1.f / 255.f);
        }
        float* pw = out + ibase + (size_t)(by0 + lrow) * IMG_W + (bx0 + bcol * 8);
        __stcs((float4*)pw,                   make_float4(Rr[0], Rr[1], Rr[2], Rr[3]));
        __stcs((float4*)(pw + 4),             make_float4(Rr[4], Rr[5], Rr[6], Rr[7]));
        __stcs((float4*)(pw + plane),         make_float4(Gg[0], Gg[1], Gg[2], Gg[3]));
        __stcs((float4*)(pw + plane + 4),     make_float4(Gg[4], Gg[5], Gg[6], Gg[7]));
        __stcs((float4*)(pw + 2 * plane),     make_float4(Bb[0], Bb[1], Bb[2], Bb[3]));
        __stcs((float4*)(pw + 2 * plane + 4), make_float4(Bb[4], Bb[5], Bb[6], Bb[7]));
    }
}

extern "C" void kernel_launch(void* const* d_in, const int* in_sizes, int n_in,
                              void* d_out, int out_size)
{
    const float* x = (const float*)d_in[0];
    float* out = (float*)d_out;
    dim3 grid(IMG_W / 32, IMG_H / 16, BATCH);
    diffjpeg_kernel<<<grid, 96>>>(x, out);
}